// round 11
// baseline (speedup 1.0000x reference)
#include <cuda_runtime.h>
#include <cuda_fp16.h>
#include <cstdint>
#include <math.h>

#define BB  64
#define TT  128
#define INS 1024
#define HH  2048
#define NG  8192              // 4*H
#define MM  (BB*TT)           // 8192
#define BTH ((size_t)BB*(size_t)TT*(size_t)HH)   // 16,777,216

// ---------------- scratch (static device allocations only) ----------------
__device__ __half g_Xh[(size_t)MM*INS];            // x in fp16            16 MB
__device__ __half g_Wxh[(size_t)NG*INS];           // Wx in fp16           16 MB
__device__ __half g_Wah[(size_t)128*64*HH];        // Wa reordered fp16    32 MB
__device__ __half g_Ah[2][(size_t)BB*HH];          // a_t ping-pong fp16
__device__ unsigned g_ctr;                         // grid-sync counter

// ---------------- helpers ----------------
__device__ __forceinline__ void cp_cg(uint32_t s, const void* g) {  // L1-bypass
    asm volatile("cp.async.cg.shared.global [%0], [%1], 16;" :: "r"(s), "l"(g));
}
#define CP_COMMIT() asm volatile("cp.async.commit_group;" ::: "memory")
#define CP_WAIT1()  asm volatile("cp.async.wait_group 1;"  ::: "memory")

__device__ __forceinline__ void ldsm4(uint32_t& r0, uint32_t& r1, uint32_t& r2, uint32_t& r3,
                                      uint32_t addr) {
    asm volatile("ldmatrix.sync.aligned.m8n8.x4.shared.b16 {%0,%1,%2,%3}, [%4];"
                 : "=r"(r0), "=r"(r1), "=r"(r2), "=r"(r3) : "r"(addr));
}

#define MMA16816(C0,C1,C2,C3,A0,A1,A2,A3,B0,B1)                                   \
    asm volatile("mma.sync.aligned.m16n8k16.row.col.f32.f16.f16.f32 "             \
                 "{%0,%1,%2,%3}, {%4,%5,%6,%7}, {%8,%9}, {%0,%1,%2,%3};"          \
                 : "+f"(C0), "+f"(C1), "+f"(C2), "+f"(C3)                         \
                 : "r"(A0), "r"(A1), "r"(A2), "r"(A3), "r"(B0), "r"(B1))

// ---------------- fused conversion kernel (1 launch) ----------------
__global__ void k_conv_all(const float* __restrict__ x, const float* __restrict__ wx,
                           const float* __restrict__ wa, const float* __restrict__ a0) {
    int i = blockIdx.x * blockDim.x + threadIdx.x;
    if (i == 0) g_ctr = 0;
    // Wa gather+convert: CTA j's 64 tile-cols {gate g, h=j*16+hh}, k-contiguous
    if (i < 128 * 64 * 1024) {
        int k2  = i & 1023;
        int rem = i >> 10;
        int n   = rem & 63;
        int j   = rem >> 6;
        int r   = (n >> 4) * HH + j * 16 + (n & 15);
        float2 v = *(const float2*)&wa[(size_t)r * HH + (size_t)k2 * 2];
        ((__half2*)g_Wah)[(size_t)(j * 64 + n) * 1024 + k2] = __floats2half2_rn(v.x, v.y);
    }
    if (i < MM * INS / 2) {
        float2 v = ((const float2*)x)[i];
        ((__half2*)g_Xh)[i] = __floats2half2_rn(v.x, v.y);
    }
    if (i < NG * INS / 2) {
        float2 v = ((const float2*)wx)[i];
        ((__half2*)g_Wxh)[i] = __floats2half2_rn(v.x, v.y);
    }
    if (i < BB * HH / 2) {
        float2 v = ((const float2*)a0)[i];
        ((__half2*)g_Ah[0])[i] = __floats2half2_rn(v.x, v.y);
    }
}

// ============================================================================
// phase 1: y_pre = x @ Wx^T + b   (unchanged — near its HMMA rate floor)
// ============================================================================
#define LD1 72                                   // halves; 144B stride
#define G_STG (2 * 128 * LD1)                    // halves per stage (A+B)
#define GEMM_SMEM (3 * G_STG * 2)                // bytes

__global__ __launch_bounds__(512) void k_gemm_x(const float* __restrict__ bias,
                                                float* __restrict__ out) {
    extern __shared__ __half sm[];
    uint32_t smb = (uint32_t)__cvta_generic_to_shared(sm);

    int tid = threadIdx.x, lane = tid & 31, wid = tid >> 5;
    int wm = wid >> 2, wn = wid & 3;                 // 4x4 warps, warp tile 32x32
    int gq = lane >> 2, tq = lane & 3;
    int m0 = blockIdx.y * 128, n0 = blockIdx.x * 128;

    int aro = lane & 15;
    int ako = (lane >> 4) * 8;

    const __half* gA = g_Xh  + (size_t)m0 * INS;
    const __half* gB = g_Wxh + (size_t)n0 * INS;

    float acc[2][4][4];
#pragma unroll
    for (int a = 0; a < 2; a++)
#pragma unroll
        for (int b = 0; b < 4; b++)
#pragma unroll
            for (int q = 0; q < 4; q++) acc[a][b][q] = 0.f;

#define G_LOAD(st, k0)                                                             \
    {                                                                              \
        uint32_t sa = smb + (uint32_t)(st) * (G_STG * 2);                          \
        uint32_t sb = sa + 128 * LD1 * 2;                                          \
        _Pragma("unroll")                                                          \
        for (int q = 0; q < 2; q++) {                                              \
            int s = tid + q * 512;                                                 \
            int row = s >> 3, c = s & 7;                                           \
            uint32_t off = (uint32_t)(row * LD1 + c * 8) * 2;                      \
            cp_cg(sa + off, gA + (size_t)row * INS + (k0) + c * 8);                \
            cp_cg(sb + off, gB + (size_t)row * INS + (k0) + c * 8);                \
        }                                                                          \
    }

    G_LOAD(0, 0);  CP_COMMIT();
    G_LOAD(1, 64); CP_COMMIT();

    for (int it = 0; it < 16; it++) {
        CP_WAIT1();
        __syncthreads();
        int nk = it + 2;
        if (nk < 16) G_LOAD(nk % 3, nk * 64);
        CP_COMMIT();

        uint32_t sA = smb + (uint32_t)(it % 3) * (G_STG * 2);
        uint32_t aBase = sA + (uint32_t)((wm * 32 + aro) * LD1 + ako) * 2;
        const __half* Bsp = sm + (size_t)(it % 3) * G_STG + 128 * LD1;
#pragma unroll
        for (int kb = 0; kb < 64; kb += 16) {
            uint32_t af[2][4], bf[4][2];
#pragma unroll
            for (int mt = 0; mt < 2; mt++)
                ldsm4(af[mt][0], af[mt][1], af[mt][2], af[mt][3],
                      aBase + (uint32_t)(mt * 16 * LD1 + kb) * 2);
#pragma unroll
            for (int nt = 0; nt < 4; nt++) {
                int cc = wn * 32 + nt * 8;
                bf[nt][0] = *(const uint32_t*)&Bsp[(cc + gq) * LD1 + kb + 2 * tq];
                bf[nt][1] = *(const uint32_t*)&Bsp[(cc + gq) * LD1 + kb + 2 * tq + 8];
            }
#pragma unroll
            for (int mt = 0; mt < 2; mt++)
#pragma unroll
                for (int nt = 0; nt < 4; nt++)
                    MMA16816(acc[mt][nt][0], acc[mt][nt][1], acc[mt][nt][2], acc[mt][nt][3],
                             af[mt][0], af[mt][1], af[mt][2], af[mt][3],
                             bf[nt][0], bf[nt][1]);
        }
    }

#pragma unroll
    for (int mt = 0; mt < 2; mt++) {
#pragma unroll
        for (int nt = 0; nt < 4; nt++) {
            int m = m0 + wm * 32 + mt * 16 + gq;
            int n = n0 + wn * 32 + nt * 8 + 2 * tq;
            int gate = n >> 11, h = n & 2047;
            float b0v = bias[n], b1v = bias[n + 1];
            float* p0 = out + (size_t)(2 + gate) * BTH + (size_t)m * HH + h;
            *(float2*)p0 = make_float2(acc[mt][nt][0] + b0v, acc[mt][nt][1] + b1v);
            float* p1 = p0 + (size_t)8 * HH;
            *(float2*)p1 = make_float2(acc[mt][nt][2] + b0v, acc[mt][nt][3] + b1v);
        }
    }
}

// ============================================================================
// phase 2: persistent recurrent kernel — now 512 threads / 16 warps (4/SMSP)
// 128 CTAs, CTA j owns h in [j*16, j*16+16) for all 4 gates (tile N=64, M=B=64).
// Warp tile 16x16 (wm 0..3 x wn 0..3); 2 HMMA/kb, ping-pong = 4 chains/warp.
// K-chunk 128 halves, 3-stage cp.async pipeline, A ldmatrix, B scalar.
// ============================================================================
#define LD2 136                                  // halves; 272B stride
#define L_STG (2 * 64 * LD2)                     // halves per stage (A+B)
#define LSTM_SMEM (3 * L_STG * 2 + 64 * 66 * 4)  // bytes (stages + yt)

__global__ __launch_bounds__(512) void k_lstm(const float* __restrict__ c0,
                                              float* __restrict__ out) {
    extern __shared__ __half sm[];
    uint32_t smb = (uint32_t)__cvta_generic_to_shared(sm);
    float* yt = (float*)(sm + 3 * L_STG);

    int tid = threadIdx.x, lane = tid & 31, wid = tid >> 5;
    int wm = wid >> 2, wn = wid & 3;                 // 4x4 warps, warp tile 16x16
    int gq = lane >> 2, tq = lane & 3;
    int j = blockIdx.x;
    int h0 = j * 16;

    int aro = lane & 15;
    int ako = (lane >> 4) * 8;

    int hh = tid & 15, mb = tid >> 4;                // mb 0..31: 2 (m,hh) pairs/thread
    float cprev[2];
#pragma unroll
    for (int p = 0; p < 2; p++)
        cprev[p] = c0[(size_t)(p * 32 + mb) * HH + h0 + hh];

    const __half* Wp = g_Wah + (size_t)j * 64 * HH;

#define L_LOAD(st, k0)                                                             \
    {                                                                              \
        uint32_t sa = smb + (uint32_t)(st) * (L_STG * 2);                          \
        uint32_t sb = sa + 64 * LD2 * 2;                                           \
        _Pragma("unroll")                                                          \
        for (int q = 0; q < 2; q++) {                                              \
            int s = tid + q * 512;                                                 \
            int row = s >> 4, c = s & 15;                                          \
            uint32_t off = (uint32_t)(row * LD2 + c * 8) * 2;                      \
            cp_cg(sa + off, Ard + (size_t)row * HH + (k0) + c * 8);                \
            cp_cg(sb + off, Wp + (size_t)row * HH + (k0) + c * 8);                 \
        }                                                                          \
    }

    for (int t = 0; t < TT; t++) {
        const __half* Ard = g_Ah[t & 1];
        __half*       Awr = g_Ah[(t + 1) & 1];

        // two accumulator sets (ping-pong over kb) -> 4 independent chains/warp
        float acc[2][2][4];
#pragma unroll
        for (int s2 = 0; s2 < 2; s2++)
#pragma unroll
            for (int b = 0; b < 2; b++)
#pragma unroll
                for (int q = 0; q < 4; q++) acc[s2][b][q] = 0.f;

        L_LOAD(0, 0);   CP_COMMIT();
        L_LOAD(1, 128); CP_COMMIT();

        // prefetch this step's y_pre slice into registers (streaming loads,
        // overlapped with the entire MMA loop; keeps Wa resident in L2)
        float yr[2][4];
#pragma unroll
        for (int p = 0; p < 2; p++) {
            size_t bofs = ((size_t)(p * 32 + mb) * TT + t) * HH + h0 + hh;
#pragma unroll
            for (int g = 0; g < 4; g++)
                yr[p][g] = __ldcs(out + (size_t)(2 + g) * BTH + bofs);
        }

        for (int it = 0; it < 16; it++) {
            CP_WAIT1();
            __syncthreads();
            int nk = it + 2;
            if (nk < 16) L_LOAD(nk % 3, nk * 128);
            CP_COMMIT();

            uint32_t sA = smb + (uint32_t)(it % 3) * (L_STG * 2);
            uint32_t aBase = sA + (uint32_t)((wm * 16 + aro) * LD2 + ako) * 2;
            const __half* Bsp = sm + (size_t)(it % 3) * L_STG + 64 * LD2;
#pragma unroll
            for (int kb = 0; kb < 128; kb += 16) {
                int s2 = (kb >> 4) & 1;              // alternate accumulator set
                uint32_t af[4], bf[2][2];
                ldsm4(af[0], af[1], af[2], af[3],
                      aBase + (uint32_t)kb * 2);
#pragma unroll
                for (int nt = 0; nt < 2; nt++) {
                    int cc = wn * 16 + nt * 8;
                    bf[nt][0] = *(const uint32_t*)&Bsp[(cc + gq) * LD2 + kb + 2 * tq];
                    bf[nt][1] = *(const uint32_t*)&Bsp[(cc + gq) * LD2 + kb + 2 * tq + 8];
                }
#pragma unroll
                for (int nt = 0; nt < 2; nt++)
                    MMA16816(acc[s2][nt][0], acc[s2][nt][1],
                             acc[s2][nt][2], acc[s2][nt][3],
                             af[0], af[1], af[2], af[3],
                             bf[nt][0], bf[nt][1]);
            }
        }

        // stage recurrent contribution (sum of both sets) into smem
#pragma unroll
        for (int nt = 0; nt < 2; nt++) {
            int r = wm * 16 + gq;
            int cc = wn * 16 + nt * 8 + 2 * tq;
            yt[r * 66 + cc]           = acc[0][nt][0] + acc[1][nt][0];
            yt[r * 66 + cc + 1]       = acc[0][nt][1] + acc[1][nt][1];
            yt[(r + 8) * 66 + cc]     = acc[0][nt][2] + acc[1][nt][2];
            yt[(r + 8) * 66 + cc + 1] = acc[0][nt][3] + acc[1][nt][3];
        }
        __syncthreads();

        // elementwise LSTM epilogue (c_t kept in registers across all 128 steps)
#pragma unroll
        for (int p = 0; p < 2; p++) {
            int m = p * 32 + mb;                     // batch index
            size_t bofs = ((size_t)m * TT + t) * HH + h0 + hh;
            float yi = yt[m * 66 + hh]      + yr[p][0];
            float yf = yt[m * 66 + 16 + hh] + yr[p][1];
            float yg = yt[m * 66 + 32 + hh] + yr[p][2];
            float yo = yt[m * 66 + 48 + hh] + yr[p][3];
            float si = 1.f / (1.f + expf(-yi));
            float sf = 1.f / (1.f + expf(-yf));
            float so = 1.f / (1.f + expf(-yo));
            float cn = sf * cprev[p] + si * tanhf(yg);
            float an = so * tanhf(cn);
            cprev[p] = cn;
            __stcs(out + 2 * BTH + bofs, yi);
            __stcs(out + 3 * BTH + bofs, yf);
            __stcs(out + 4 * BTH + bofs, yg);
            __stcs(out + 5 * BTH + bofs, yo);
            __stcs(out + bofs, an);
            __stcs(out + BTH + bofs, cn);
            Awr[(size_t)m * HH + h0 + hh] = __float2half_rn(an);
        }

        // grid-wide sync so every CTA sees a_t before starting step t+1
        if (t < TT - 1) {
            __threadfence();                         // release a_t writes
            __syncthreads();
            if (tid == 0) {
                atomicAdd(&g_ctr, 1u);
                unsigned tgt = (unsigned)(t + 1) * (unsigned)gridDim.x;
                unsigned v;
                do {
                    asm volatile("ld.global.cg.u32 %0, [%1];" : "=r"(v) : "l"(&g_ctr) : "memory");
                    if (v < tgt) __nanosleep(32);
                } while (v < tgt);
                __threadfence();
            }
            __syncthreads();
        }
    }
}

// ---------------- launch ----------------
extern "C" void kernel_launch(void* const* d_in, const int* in_sizes, int n_in,
                              void* d_out, int out_size) {
    (void)in_sizes; (void)n_in; (void)out_size;
    const float* x  = (const float*)d_in[0];
    const float* Wx = (const float*)d_in[1];
    const float* Wa = (const float*)d_in[2];
    const float* b  = (const float*)d_in[3];
    const float* a0 = (const float*)d_in[4];
    const float* c0 = (const float*)d_in[5];
    float* out = (float*)d_out;

    cudaFuncSetAttribute(k_gemm_x, cudaFuncAttributeMaxDynamicSharedMemorySize, GEMM_SMEM);
    cudaFuncSetAttribute(k_lstm,   cudaFuncAttributeMaxDynamicSharedMemorySize, LSTM_SMEM);

    int nconv = 128 * 64 * 1024;                 // largest section (Wa half2 count)
    k_conv_all<<<(nconv + 255) / 256, 256>>>(x, Wx, Wa, a0);
    k_gemm_x<<<dim3(64, 64), 512, GEMM_SMEM>>>(b, out);
    k_lstm<<<128, 512, LSTM_SMEM>>>(c0, out);
}

// round 13
// speedup vs baseline: 1.0976x; 1.0976x over previous
#include <cuda_runtime.h>
#include <cuda_fp16.h>
#include <cstdint>
#include <math.h>

#define BB  64
#define TT  128
#define INS 1024
#define HH  2048
#define NG  8192              // 4*H
#define MM  (BB*TT)           // 8192
#define BTH ((size_t)BB*(size_t)TT*(size_t)HH)   // 16,777,216

// ---------------- scratch (static device allocations only) ----------------
__device__ __half g_Xh[(size_t)MM*INS];            // x in fp16            16 MB
__device__ __half g_Wxh[(size_t)NG*INS];           // Wx in fp16           16 MB
__device__ __half g_Wah[(size_t)128*64*HH];        // Wa reordered fp16    32 MB
__device__ __half g_Ah[2][(size_t)BB*HH];          // a_t ping-pong fp16
__device__ unsigned g_ctr;                         // grid-sync counter

// ---------------- helpers ----------------
__device__ __forceinline__ void cp_cg(uint32_t s, const void* g) {  // L1-bypass
    asm volatile("cp.async.cg.shared.global [%0], [%1], 16;" :: "r"(s), "l"(g));
}
#define CP_COMMIT() asm volatile("cp.async.commit_group;" ::: "memory")
#define CP_WAIT1()  asm volatile("cp.async.wait_group 1;"  ::: "memory")

__device__ __forceinline__ void ldsm4(uint32_t& r0, uint32_t& r1, uint32_t& r2, uint32_t& r3,
                                      uint32_t addr) {
    asm volatile("ldmatrix.sync.aligned.m8n8.x4.shared.b16 {%0,%1,%2,%3}, [%4];"
                 : "=r"(r0), "=r"(r1), "=r"(r2), "=r"(r3) : "r"(addr));
}

#define MMA16816(C0,C1,C2,C3,A0,A1,A2,A3,B0,B1)                                   \
    asm volatile("mma.sync.aligned.m16n8k16.row.col.f32.f16.f16.f32 "             \
                 "{%0,%1,%2,%3}, {%4,%5,%6,%7}, {%8,%9}, {%0,%1,%2,%3};"          \
                 : "+f"(C0), "+f"(C1), "+f"(C2), "+f"(C3)                         \
                 : "r"(A0), "r"(A1), "r"(A2), "r"(A3), "r"(B0), "r"(B1))

// ---------------- fused conversion kernel (1 launch) ----------------
__global__ void k_conv_all(const float* __restrict__ x, const float* __restrict__ wx,
                           const float* __restrict__ wa, const float* __restrict__ a0) {
    int i = blockIdx.x * blockDim.x + threadIdx.x;
    if (i == 0) g_ctr = 0;
    // Wa gather+convert: CTA j's 64 tile-cols {gate g, h=j*16+hh}, k-contiguous
    if (i < 128 * 64 * 1024) {
        int k2  = i & 1023;
        int rem = i >> 10;
        int n   = rem & 63;
        int j   = rem >> 6;
        int r   = (n >> 4) * HH + j * 16 + (n & 15);
        float2 v = *(const float2*)&wa[(size_t)r * HH + (size_t)k2 * 2];
        ((__half2*)g_Wah)[(size_t)(j * 64 + n) * 1024 + k2] = __floats2half2_rn(v.x, v.y);
    }
    if (i < MM * INS / 2) {
        float2 v = ((const float2*)x)[i];
        ((__half2*)g_Xh)[i] = __floats2half2_rn(v.x, v.y);
    }
    if (i < NG * INS / 2) {
        float2 v = ((const float2*)wx)[i];
        ((__half2*)g_Wxh)[i] = __floats2half2_rn(v.x, v.y);
    }
    if (i < BB * HH / 2) {
        float2 v = ((const float2*)a0)[i];
        ((__half2*)g_Ah[0])[i] = __floats2half2_rn(v.x, v.y);
    }
}

// ============================================================================
// phase 1: y_pre = x @ Wx^T + b   (unchanged — at its HMMA rate floor)
// ============================================================================
#define LD1 72                                   // halves; 144B stride
#define G_STG (2 * 128 * LD1)                    // halves per stage (A+B)
#define GEMM_SMEM (3 * G_STG * 2)                // bytes

__global__ __launch_bounds__(512) void k_gemm_x(const float* __restrict__ bias,
                                                float* __restrict__ out) {
    extern __shared__ __half sm[];
    uint32_t smb = (uint32_t)__cvta_generic_to_shared(sm);

    int tid = threadIdx.x, lane = tid & 31, wid = tid >> 5;
    int wm = wid >> 2, wn = wid & 3;                 // 4x4 warps, warp tile 32x32
    int gq = lane >> 2, tq = lane & 3;
    int m0 = blockIdx.y * 128, n0 = blockIdx.x * 128;

    int aro = lane & 15;
    int ako = (lane >> 4) * 8;

    const __half* gA = g_Xh  + (size_t)m0 * INS;
    const __half* gB = g_Wxh + (size_t)n0 * INS;

    float acc[2][4][4];
#pragma unroll
    for (int a = 0; a < 2; a++)
#pragma unroll
        for (int b = 0; b < 4; b++)
#pragma unroll
            for (int q = 0; q < 4; q++) acc[a][b][q] = 0.f;

#define G_LOAD(st, k0)                                                             \
    {                                                                              \
        uint32_t sa = smb + (uint32_t)(st) * (G_STG * 2);                          \
        uint32_t sb = sa + 128 * LD1 * 2;                                          \
        _Pragma("unroll")                                                          \
        for (int q = 0; q < 2; q++) {                                              \
            int s = tid + q * 512;                                                 \
            int row = s >> 3, c = s & 7;                                           \
            uint32_t off = (uint32_t)(row * LD1 + c * 8) * 2;                      \
            cp_cg(sa + off, gA + (size_t)row * INS + (k0) + c * 8);                \
            cp_cg(sb + off, gB + (size_t)row * INS + (k0) + c * 8);                \
        }                                                                          \
    }

    G_LOAD(0, 0);  CP_COMMIT();
    G_LOAD(1, 64); CP_COMMIT();

    for (int it = 0; it < 16; it++) {
        CP_WAIT1();
        __syncthreads();
        int nk = it + 2;
        if (nk < 16) G_LOAD(nk % 3, nk * 64);
        CP_COMMIT();

        uint32_t sA = smb + (uint32_t)(it % 3) * (G_STG * 2);
        uint32_t aBase = sA + (uint32_t)((wm * 32 + aro) * LD1 + ako) * 2;
        const __half* Bsp = sm + (size_t)(it % 3) * G_STG + 128 * LD1;
#pragma unroll
        for (int kb = 0; kb < 64; kb += 16) {
            uint32_t af[2][4], bf[4][2];
#pragma unroll
            for (int mt = 0; mt < 2; mt++)
                ldsm4(af[mt][0], af[mt][1], af[mt][2], af[mt][3],
                      aBase + (uint32_t)(mt * 16 * LD1 + kb) * 2);
#pragma unroll
            for (int nt = 0; nt < 4; nt++) {
                int cc = wn * 32 + nt * 8;
                bf[nt][0] = *(const uint32_t*)&Bsp[(cc + gq) * LD1 + kb + 2 * tq];
                bf[nt][1] = *(const uint32_t*)&Bsp[(cc + gq) * LD1 + kb + 2 * tq + 8];
            }
#pragma unroll
            for (int mt = 0; mt < 2; mt++)
#pragma unroll
                for (int nt = 0; nt < 4; nt++)
                    MMA16816(acc[mt][nt][0], acc[mt][nt][1], acc[mt][nt][2], acc[mt][nt][3],
                             af[mt][0], af[mt][1], af[mt][2], af[mt][3],
                             bf[nt][0], bf[nt][1]);
        }
    }

#pragma unroll
    for (int mt = 0; mt < 2; mt++) {
#pragma unroll
        for (int nt = 0; nt < 4; nt++) {
            int m = m0 + wm * 32 + mt * 16 + gq;
            int n = n0 + wn * 32 + nt * 8 + 2 * tq;
            int gate = n >> 11, h = n & 2047;
            float b0v = bias[n], b1v = bias[n + 1];
            float* p0 = out + (size_t)(2 + gate) * BTH + (size_t)m * HH + h;
            *(float2*)p0 = make_float2(acc[mt][nt][0] + b0v, acc[mt][nt][1] + b1v);
            float* p1 = p0 + (size_t)8 * HH;
            *(float2*)p1 = make_float2(acc[mt][nt][2] + b0v, acc[mt][nt][3] + b1v);
        }
    }
}

// ============================================================================
// phase 2: persistent recurrent kernel — round-10 shape, K-chunk 256.
// 128 CTAs, 256 threads (8 warps, 2x4, warp tile 32x16), CTA j owns h-slice 16.
// K-chunk 256 halves -> 8 pipeline iterations/step (half the barrier count).
// 3-stage cp.async pipeline, A ldmatrix, B scalar, acc ping-pong (8 chains/warp).
// ============================================================================
#define KC2  256                                 // K-chunk (halves)
#define LD2  264                                 // halves; 528B stride (=16 mod 128)
#define L_STG (2 * 64 * LD2)                     // halves per stage (A+B) = 33792
#define LSTM_SMEM (3 * L_STG * 2 + 64 * 66 * 4)  // 202752 + 16896 = 219648 B

__global__ __launch_bounds__(256) void k_lstm(const float* __restrict__ c0,
                                              float* __restrict__ out) {
    extern __shared__ __half sm[];
    uint32_t smb = (uint32_t)__cvta_generic_to_shared(sm);
    float* yt = (float*)(sm + 3 * L_STG);

    int tid = threadIdx.x, lane = tid & 31, wid = tid >> 5;
    int wm = wid >> 2, wn = wid & 3;                 // 2x4 warps, warp tile 32x16
    int gq = lane >> 2, tq = lane & 3;
    int j = blockIdx.x;
    int h0 = j * 16;

    int aro = lane & 15;
    int ako = (lane >> 4) * 8;

    int hh = tid & 15, mb = tid >> 4;                // epilogue: 4 (m,hh) pairs/thread
    float cprev[4];
#pragma unroll
    for (int p = 0; p < 4; p++)
        cprev[p] = c0[(size_t)(p * 16 + mb) * HH + h0 + hh];

    const __half* Wp = g_Wah + (size_t)j * 64 * HH;

    // chunk loader: A(64 x 256) + B(64 x 256) halves; 64 rows x 32 16B-slots each
#define L_LOAD(st, k0)                                                             \
    {                                                                              \
        uint32_t sa = smb + (uint32_t)(st) * (L_STG * 2);                          \
        uint32_t sb = sa + 64 * LD2 * 2;                                           \
        _Pragma("unroll")                                                          \
        for (int q = 0; q < 8; q++) {                                              \
            int s = tid + q * 256;                                                 \
            int row = s >> 5, c = s & 31;                                          \
            uint32_t off = (uint32_t)(row * LD2 + c * 8) * 2;                      \
            cp_cg(sa + off, Ard + (size_t)row * HH + (k0) + c * 8);                \
            cp_cg(sb + off, Wp + (size_t)row * HH + (k0) + c * 8);                 \
        }                                                                          \
    }

    for (int t = 0; t < TT; t++) {
        const __half* Ard = g_Ah[t & 1];
        __half*       Awr = g_Ah[(t + 1) & 1];

        // two accumulator sets (ping-pong over kb) -> 8 independent chains/warp
        float acc[2][2][2][4];
#pragma unroll
        for (int s2 = 0; s2 < 2; s2++)
#pragma unroll
            for (int a = 0; a < 2; a++)
#pragma unroll
                for (int b = 0; b < 2; b++)
#pragma unroll
                    for (int q = 0; q < 4; q++) acc[s2][a][b][q] = 0.f;

        L_LOAD(0, 0);    CP_COMMIT();
        L_LOAD(1, KC2);  CP_COMMIT();

        // prefetch this step's y_pre slice into registers (streaming loads,
        // overlapped with the entire MMA loop; keeps Wa resident in L2)
        float yr[4][4];
#pragma unroll
        for (int p = 0; p < 4; p++) {
            size_t bofs = ((size_t)(p * 16 + mb) * TT + t) * HH + h0 + hh;
#pragma unroll
            for (int g = 0; g < 4; g++)
                yr[p][g] = __ldcs(out + (size_t)(2 + g) * BTH + bofs);
        }

        for (int it = 0; it < 8; it++) {
            CP_WAIT1();
            __syncthreads();
            int nk = it + 2;
            if (nk < 8) L_LOAD(nk % 3, nk * KC2);
            CP_COMMIT();

            uint32_t sA = smb + (uint32_t)(it % 3) * (L_STG * 2);
            uint32_t aBase = sA + (uint32_t)((wm * 32 + aro) * LD2 + ako) * 2;
            const __half* Bsp = sm + (size_t)(it % 3) * L_STG + 64 * LD2;
#pragma unroll
            for (int kb = 0; kb < KC2; kb += 16) {
                int s2 = (kb >> 4) & 1;              // alternate accumulator set
                uint32_t af[2][4], bf[2][2];
#pragma unroll
                for (int mt = 0; mt < 2; mt++)
                    ldsm4(af[mt][0], af[mt][1], af[mt][2], af[mt][3],
                          aBase + (uint32_t)(mt * 16 * LD2 + kb) * 2);
#pragma unroll
                for (int nt = 0; nt < 2; nt++) {
                    int cc = wn * 16 + nt * 8;
                    bf[nt][0] = *(const uint32_t*)&Bsp[(cc + gq) * LD2 + kb + 2 * tq];
                    bf[nt][1] = *(const uint32_t*)&Bsp[(cc + gq) * LD2 + kb + 2 * tq + 8];
                }
#pragma unroll
                for (int mt = 0; mt < 2; mt++)
#pragma unroll
                    for (int nt = 0; nt < 2; nt++)
                        MMA16816(acc[s2][mt][nt][0], acc[s2][mt][nt][1],
                                 acc[s2][mt][nt][2], acc[s2][mt][nt][3],
                                 af[mt][0], af[mt][1], af[mt][2], af[mt][3],
                                 bf[nt][0], bf[nt][1]);
            }
        }

        // stage recurrent contribution (sum of both sets) into smem
#pragma unroll
        for (int mt = 0; mt < 2; mt++) {
#pragma unroll
            for (int nt = 0; nt < 2; nt++) {
                int r = wm * 32 + mt * 16 + gq;
                int cc = wn * 16 + nt * 8 + 2 * tq;
                yt[r * 66 + cc]           = acc[0][mt][nt][0] + acc[1][mt][nt][0];
                yt[r * 66 + cc + 1]       = acc[0][mt][nt][1] + acc[1][mt][nt][1];
                yt[(r + 8) * 66 + cc]     = acc[0][mt][nt][2] + acc[1][mt][nt][2];
                yt[(r + 8) * 66 + cc + 1] = acc[0][mt][nt][3] + acc[1][mt][nt][3];
            }
        }
        __syncthreads();

        // elementwise LSTM epilogue (c_t kept in registers across all 128 steps)
#pragma unroll
        for (int p = 0; p < 4; p++) {
            int m = p * 16 + mb;                     // batch index
            size_t bofs = ((size_t)m * TT + t) * HH + h0 + hh;
            float yi = yt[m * 66 + hh]      + yr[p][0];
            float yf = yt[m * 66 + 16 + hh] + yr[p][1];
            float yg = yt[m * 66 + 32 + hh] + yr[p][2];
            float yo = yt[m * 66 + 48 + hh] + yr[p][3];
            float si = 1.f / (1.f + expf(-yi));
            float sf = 1.f / (1.f + expf(-yf));
            float so = 1.f / (1.f + expf(-yo));
            float cn = sf * cprev[p] + si * tanhf(yg);
            float an = so * tanhf(cn);
            cprev[p] = cn;
            __stcs(out + 2 * BTH + bofs, yi);
            __stcs(out + 3 * BTH + bofs, yf);
            __stcs(out + 4 * BTH + bofs, yg);
            __stcs(out + 5 * BTH + bofs, yo);
            __stcs(out + bofs, an);
            __stcs(out + BTH + bofs, cn);
            Awr[(size_t)m * HH + h0 + hh] = __float2half_rn(an);
        }

        // grid-wide sync so every CTA sees a_t before starting step t+1
        if (t < TT - 1) {
            __threadfence();                         // release a_t writes
            __syncthreads();
            if (tid == 0) {
                atomicAdd(&g_ctr, 1u);
                unsigned tgt = (unsigned)(t + 1) * (unsigned)gridDim.x;
                unsigned v;
                do {
                    asm volatile("ld.global.cg.u32 %0, [%1];" : "=r"(v) : "l"(&g_ctr) : "memory");
                    if (v < tgt) __nanosleep(32);
                } while (v < tgt);
                __threadfence();
            }
            __syncthreads();
        }
    }
}

// ---------------- launch ----------------
extern "C" void kernel_launch(void* const* d_in, const int* in_sizes, int n_in,
                              void* d_out, int out_size) {
    (void)in_sizes; (void)n_in; (void)out_size;
    const float* x  = (const float*)d_in[0];
    const float* Wx = (const float*)d_in[1];
    const float* Wa = (const float*)d_in[2];
    const float* b  = (const float*)d_in[3];
    const float* a0 = (const float*)d_in[4];
    const float* c0 = (const float*)d_in[5];
    float* out = (float*)d_out;

    cudaFuncSetAttribute(k_gemm_x, cudaFuncAttributeMaxDynamicSharedMemorySize, GEMM_SMEM);
    cudaFuncSetAttribute(k_lstm,   cudaFuncAttributeMaxDynamicSharedMemorySize, LSTM_SMEM);

    int nconv = 128 * 64 * 1024;                 // largest section (Wa half2 count)
    k_conv_all<<<(nconv + 255) / 256, 256>>>(x, Wx, Wa, a0);
    k_gemm_x<<<dim3(64, 64), 512, GEMM_SMEM>>>(b, out);
    k_lstm<<<128, 256, LSTM_SMEM>>>(c0, out);
}